// round 7
// baseline (speedup 1.0000x reference)
#include <cuda_runtime.h>
#include <cuda_fp16.h>

#define MAX_NODES 500000
#define MAX_EDGES 8000000
#define MAX_GRAPHS 8192
#define FDIM 16
#define SCAN_BS 1024
#define MAX_SCAN_BLOCKS 1024

__device__ int    g_cnt_i[MAX_NODES];            // in-degree (memset to 0)
__device__ int    g_off[MAX_NODES + 1];          // CSR offsets (absolute)
__device__ int    g_cursor[MAX_NODES];           // fill cursors
__device__ int    g_part[MAX_SCAN_BLOCKS];
__device__ int    g_srcs[MAX_EDGES];             // CSR sources grouped by target
__device__ __half g_h[MAX_NODES * FDIM];         // layer1 h*dinv, fp16
__device__ __half g_h2[MAX_NODES * FDIM];        // layer2 h*dinv, fp16
__device__ float  g_agg[MAX_NODES * FDIM];       // gather0 output (fp32 sums)
__device__ float  g_pool[MAX_GRAPHS * FDIM];
__device__ float  g_gcnt[MAX_GRAPHS];

__device__ __forceinline__ void red_v2(float* addr, float2 v) {
    asm volatile("red.global.add.v2.f32 [%0], {%1,%2};"
                 :: "l"(addr), "f"(v.x), "f"(v.y) : "memory");
}

// pack 16 fp32 (scaled by di) -> 32B fp16
__device__ __forceinline__ void store_h16(__half* dst, const float* s, float di) {
    __align__(16) __half2 hh[8];
#pragma unroll
    for (int q = 0; q < 8; q++)
        hh[q] = __floats2half2_rn(s[2 * q] * di, s[2 * q + 1] * di);
    *(uint4*)dst       = *(uint4*)&hh[0];
    *(uint4*)(dst + 8) = *(uint4*)&hh[4];
}

// 1) in-degree count
__global__ void k_count(const int* __restrict__ cols, int E) {
    int e = blockIdx.x * blockDim.x + threadIdx.x;
    if (e < E) atomicAdd(&g_cnt_i[cols[e]], 1);
}

// 2) block-level exclusive scan
__global__ void k_scan1(int N) {
    __shared__ int sm[SCAN_BS];
    int tid = threadIdx.x;
    int i = blockIdx.x * SCAN_BS + tid;
    int v = (i < N) ? g_cnt_i[i] : 0;
    sm[tid] = v;
    __syncthreads();
    for (int off = 1; off < SCAN_BS; off <<= 1) {
        int t = (tid >= off) ? sm[tid - off] : 0;
        __syncthreads();
        sm[tid] += t;
        __syncthreads();
    }
    if (i < N) g_off[i] = sm[tid] - v;
    if (tid == SCAN_BS - 1) g_part[blockIdx.x] = sm[tid];
}

// 3) scan of block totals
__global__ void k_scan2(int NB) {
    __shared__ int sm[SCAN_BS];
    int tid = threadIdx.x;
    int v = (tid < NB) ? g_part[tid] : 0;
    sm[tid] = v;
    __syncthreads();
    for (int off = 1; off < SCAN_BS; off <<= 1) {
        int t = (tid >= off) ? sm[tid - off] : 0;
        __syncthreads();
        sm[tid] += t;
        __syncthreads();
    }
    if (tid < NB) g_part[tid] = sm[tid] - v;
}

// 4) finalize absolute offsets + cursors
__global__ void k_scan3(int N, int E) {
    int i = blockIdx.x * blockDim.x + threadIdx.x;
    if (i < N) {
        int v = g_off[i] + g_part[i >> 10];
        g_off[i] = v;
        g_cursor[i] = v;
    }
    if (i == 0) g_off[N] = E;
}

// 5) fill via atomic cursor
__global__ void k_fill(const int* __restrict__ rows, const int* __restrict__ cols,
                       int E) {
    int e = blockIdx.x * blockDim.x + threadIdx.x;
    if (e >= E) return;
    int p = atomicAdd(&g_cursor[cols[e]], 1);
    g_srcs[p] = rows[e];
}

// 6) layer1 dense: g_h = fp16((x @ W1) * dinv)
__global__ void k_layer1(const float* __restrict__ x, const float* __restrict__ W1,
                         int N) {
    __shared__ float sx[128 * 9];
    int base = blockIdx.x * 128;
    int n = base + threadIdx.x;
    int lim = min(128, N - base) * 9;
    for (int i = threadIdx.x; i < lim; i += 128)
        sx[i] = x[(long long)base * 9 + i];
    __syncthreads();
    if (n >= N) return;
    float xi[9];
#pragma unroll
    for (int k = 0; k < 9; k++) xi[k] = sx[threadIdx.x * 9 + k];
    float di = rsqrtf((float)g_cnt_i[n] + 1.0f);
    float s[FDIM];
#pragma unroll
    for (int f = 0; f < FDIM; f++) {
        float acc = 0.0f;
#pragma unroll
        for (int k = 0; k < 9; k++) acc += xi[k] * __ldg(&W1[k * FDIM + f]);
        s[f] = acc;
    }
    store_h16(&g_h[n * FDIM], s, di);
}

// 7/9) CSR gather, one warp per node.
// lane = grp(0..3) * 8 + pair(0..7). Coalesced block-load of 32 src indices,
// shfl-distributed; 4 edges per warp-load (8 lanes x half2 = one 32B row each).
// Fixed-trip predicated inner loop -> fully unrolled -> MLP ~8.
template <int PASS>
__global__ void k_gather(const int* __restrict__ batch,
                         const float* __restrict__ b2, int N) {
    int warp = (blockIdx.x * blockDim.x + threadIdx.x) >> 5;
    if (warp >= N) return;
    int lane = threadIdx.x & 31;
    int p = lane & 7;        // feature pair
    int grp = lane >> 3;     // edge subgroup
    const __half* H = (PASS == 0) ? g_h : g_h2;
    int s0 = __ldg(&g_off[warp]), s1 = __ldg(&g_off[warp + 1]);
    float2 acc = make_float2(0.f, 0.f);
    if (grp == 0) {  // self-loop
        float2 f = __half22float2(*(const __half2*)&H[warp * FDIM + p * 2]);
        acc.x += f.x; acc.y += f.y;
    }
    for (int base = s0; base < s1; base += 32) {
        int idx = base + lane;
        int rk = (idx < s1) ? __ldg(&g_srcs[idx]) : 0;
        int m = min(32, s1 - base);
#pragma unroll
        for (int k = 0; k < 32; k += 4) {
            int kk = k + grp;
            int r = __shfl_sync(0xffffffffu, rk, kk);
            if (kk < m) {
                float2 f = __half22float2(*(const __half2*)&H[r * FDIM + p * 2]);
                acc.x += f.x; acc.y += f.y;
            }
        }
    }
    // reduce across the 4 edge subgroups
    acc.x += __shfl_xor_sync(0xffffffffu, acc.x, 8);
    acc.y += __shfl_xor_sync(0xffffffffu, acc.y, 8);
    acc.x += __shfl_xor_sync(0xffffffffu, acc.x, 16);
    acc.y += __shfl_xor_sync(0xffffffffu, acc.y, 16);

    if (PASS == 0) {
        if (grp == 0) *(float2*)&g_agg[warp * FDIM + p * 2] = acc;
    } else {
        float di = rsqrtf((float)(s1 - s0) + 1.0f);
        if (grp == 0) {
            float2 a;
            a.x = fmaxf(acc.x * di + __ldg(&b2[p * 2 + 0]), 0.0f);
            a.y = fmaxf(acc.y * di + __ldg(&b2[p * 2 + 1]), 0.0f);
            red_v2(&g_pool[__ldg(&batch[warp]) * FDIM + p * 2], a);
        } else if (lane == 8) {
            atomicAdd(&g_gcnt[__ldg(&batch[warp])], 1.0f);
        }
    }
}

// 8) transform: a = relu(agg*di + b1); g_h2 = fp16((a @ W2) * di); W2 in smem
__global__ void k_transform(const float* __restrict__ b1, const float* __restrict__ W2,
                            int N) {
    __shared__ float sW[FDIM * FDIM];
    if (threadIdx.x < FDIM * FDIM) sW[threadIdx.x] = W2[threadIdx.x];
    __syncthreads();
    int n = blockIdx.x * blockDim.x + threadIdx.x;
    if (n >= N) return;
    float di = rsqrtf((float)g_cnt_i[n] + 1.0f);
    float a[FDIM];
    const float4* ain = (const float4*)&g_agg[n * FDIM];
#pragma unroll
    for (int qq = 0; qq < 4; qq++) {
        float4 v = ain[qq];
        a[qq*4+0] = fmaxf(v.x * di + __ldg(&b1[qq*4+0]), 0.0f);
        a[qq*4+1] = fmaxf(v.y * di + __ldg(&b1[qq*4+1]), 0.0f);
        a[qq*4+2] = fmaxf(v.z * di + __ldg(&b1[qq*4+2]), 0.0f);
        a[qq*4+3] = fmaxf(v.w * di + __ldg(&b1[qq*4+3]), 0.0f);
    }
    float s[FDIM];
#pragma unroll
    for (int f = 0; f < FDIM; f++) {
        float acc = 0.0f;
#pragma unroll
        for (int k = 0; k < FDIM; k++) acc += a[k] * sW[k * FDIM + f];
        s[f] = acc;
    }
    store_h16(&g_h2[n * FDIM], s, di);
}

// 10) MLP head
__global__ void k_mlp(const float* __restrict__ meta,
                      const float* __restrict__ Wh1, const float* __restrict__ bh1,
                      const float* __restrict__ Wh2, const float* __restrict__ bh2,
                      float* __restrict__ out, int G) {
    int g = blockIdx.x * blockDim.x + threadIdx.x;
    if (g >= G) return;
    float inv = 1.0f / fmaxf(g_gcnt[g], 1.0f);
    float z[FDIM];
#pragma unroll
    for (int f = 0; f < FDIM; f++) z[f] = __ldg(&bh1[f]);
#pragma unroll
    for (int k = 0; k < FDIM; k++) {
        float e = g_pool[g * FDIM + k] * inv;
#pragma unroll
        for (int f = 0; f < FDIM; f++) z[f] += e * __ldg(&Wh1[k * FDIM + f]);
    }
    for (int k = 0; k < 27; k++) {
        float m = meta[g * 27 + k];
#pragma unroll
        for (int f = 0; f < FDIM; f++) z[f] += m * __ldg(&Wh1[(FDIM + k) * FDIM + f]);
    }
    float o = __ldg(&bh2[0]);
#pragma unroll
    for (int f = 0; f < FDIM; f++) o += fmaxf(z[f], 0.0f) * __ldg(&Wh2[f]);
    out[g] = o;
}

extern "C" void kernel_launch(void* const* d_in, const int* in_sizes, int n_in,
                              void* d_out, int out_size) {
    const float* x    = (const float*)d_in[0];
    const int*   ei   = (const int*)d_in[1];
    const int*   batch= (const int*)d_in[2];
    const float* meta = (const float*)d_in[3];
    const float* W1   = (const float*)d_in[4];
    const float* b1   = (const float*)d_in[5];
    const float* W2   = (const float*)d_in[6];
    const float* b2   = (const float*)d_in[7];
    const float* Wh1  = (const float*)d_in[8];
    const float* bh1  = (const float*)d_in[9];
    const float* Wh2  = (const float*)d_in[10];
    const float* bh2  = (const float*)d_in[11];
    float* out = (float*)d_out;

    const int N = in_sizes[0] / 9;
    const int E = in_sizes[1] / 2;
    const int G = in_sizes[3] / 27;
    const int* rows = ei;      // source
    const int* cols = ei + E;  // target

    const int B = 256;
    const int NB_SCAN = (N + SCAN_BS - 1) / SCAN_BS;

    void *p_cnt, *p_pool, *p_gcnt;
    cudaGetSymbolAddress(&p_cnt, g_cnt_i);
    cudaGetSymbolAddress(&p_pool, g_pool);
    cudaGetSymbolAddress(&p_gcnt, g_gcnt);
    cudaMemsetAsync(p_cnt, 0, (size_t)N * sizeof(int));
    cudaMemsetAsync(p_pool, 0, (size_t)G * FDIM * sizeof(float));
    cudaMemsetAsync(p_gcnt, 0, (size_t)G * sizeof(float));

    k_count<<<(E + B - 1) / B, B>>>(cols, E);
    k_scan1<<<NB_SCAN, SCAN_BS>>>(N);
    k_scan2<<<1, SCAN_BS>>>(NB_SCAN);
    k_scan3<<<(N + B - 1) / B, B>>>(N, E);
    k_fill<<<(E + B - 1) / B, B>>>(rows, cols, E);
    k_layer1<<<(N + 127) / 128, 128>>>(x, W1, N);
    {
        long long t = (long long)N * 32;
        int nb = (int)((t + B - 1) / B);
        k_gather<0><<<nb, B>>>(batch, b2, N);
        k_transform<<<(N + B - 1) / B, B>>>(b1, W2, N);
        k_gather<1><<<nb, B>>>(batch, b2, N);
    }
    k_mlp<<<(G + B - 1) / B, B>>>(meta, Wh1, bh1, Wh2, bh2, out, G);
}

// round 8
// speedup vs baseline: 1.5335x; 1.5335x over previous
#include <cuda_runtime.h>
#include <cuda_fp16.h>

#define MAX_NODES 500000
#define MAX_GRAPHS 8192
#define FDIM 16

__device__ int    g_cnt_i[MAX_NODES];        // in-degree (memset 0)
__device__ __half g_h[MAX_NODES * FDIM];     // current layer features * dinv (fp16)
__device__ float  g_agg[MAX_NODES * FDIM];   // accumulator (init = self-loop term)
__device__ float  g_pool[MAX_GRAPHS * FDIM];
__device__ float  g_gcnt[MAX_GRAPHS];

__device__ __forceinline__ void red_v4(float* addr, float4 v) {
    asm volatile("red.global.add.v4.f32 [%0], {%1,%2,%3,%4};"
                 :: "l"(addr), "f"(v.x), "f"(v.y), "f"(v.z), "f"(v.w)
                 : "memory");
}

// pack 16 scaled fp32 -> 32B fp16
__device__ __forceinline__ void store_h16(__half* dst, const float* s, float di) {
    __align__(16) __half2 hh[8];
#pragma unroll
    for (int q = 0; q < 8; q++)
        hh[q] = __floats2half2_rn(s[2 * q] * di, s[2 * q + 1] * di);
    *(uint4*)dst       = *(uint4*)&hh[0];
    *(uint4*)(dst + 8) = *(uint4*)&hh[4];
}

// 1) in-degree count over targets
__global__ void k_count(const int* __restrict__ cols, int E) {
    int e = blockIdx.x * blockDim.x + threadIdx.x;
    if (e < E) atomicAdd(&g_cnt_i[cols[e]], 1);
}

// 2) layer1: s = x@W1 ; g_h = fp16(s*di) ; g_agg = s*di (self-loop, pre-dinv_c)
__global__ void k_layer1(const float* __restrict__ x, const float* __restrict__ W1,
                         int N) {
    __shared__ float sx[128 * 9];
    int base = blockIdx.x * 128;
    int n = base + threadIdx.x;
    int lim = min(128, N - base) * 9;
    for (int i = threadIdx.x; i < lim; i += 128)
        sx[i] = x[(long long)base * 9 + i];
    __syncthreads();
    if (n >= N) return;
    float xi[9];
#pragma unroll
    for (int k = 0; k < 9; k++) xi[k] = sx[threadIdx.x * 9 + k];
    float di = rsqrtf((float)g_cnt_i[n] + 1.0f);
    float s[FDIM];
#pragma unroll
    for (int f = 0; f < FDIM; f++) {
        float acc = 0.0f;
#pragma unroll
        for (int k = 0; k < 9; k++) acc += xi[k] * __ldg(&W1[k * FDIM + f]);
        s[f] = acc;
    }
    store_h16(&g_h[n * FDIM], s, di);
    float4* ap = (float4*)&g_agg[n * FDIM];
#pragma unroll
    for (int q = 0; q < 4; q++)
        ap[q] = make_float4(s[q*4+0]*di, s[q*4+1]*di, s[q*4+2]*di, s[q*4+3]*di);
}

// 3/5) scatter: agg[c] += g_h[r]   (dinv_c applied later per node)
//      4 lanes/edge: each lane loads 8B fp16 (4 feats) -> one red.v4.
__global__ void k_scatter(const int* __restrict__ rows,
                          const int* __restrict__ cols, int E) {
    long long idx = (long long)blockIdx.x * blockDim.x + threadIdx.x;
    int e = (int)(idx >> 2);
    int q = (int)(idx & 3);
    if (e >= E) return;
    int r = __ldg(&rows[e]);
    int c = __ldg(&cols[e]);
    uint2 u = *(const uint2*)&g_h[r * FDIM + q * 4];
    float2 f0 = __half22float2(*(__half2*)&u.x);
    float2 f1 = __half22float2(*(__half2*)&u.y);
    red_v4(&g_agg[c * FDIM + q * 4], make_float4(f0.x, f0.y, f1.x, f1.y));
}

// 4) transform: a = relu(agg*di + b1); s = a@W2; g_h = fp16(s*di); g_agg = s*di
__global__ void k_transform(const float* __restrict__ b1, const float* __restrict__ W2,
                            int N) {
    __shared__ float sW[FDIM * FDIM];
    if (threadIdx.x < FDIM * FDIM) sW[threadIdx.x] = W2[threadIdx.x];
    __syncthreads();
    int n = blockIdx.x * blockDim.x + threadIdx.x;
    if (n >= N) return;
    float di = rsqrtf((float)g_cnt_i[n] + 1.0f);
    float a[FDIM];
    const float4* ain = (const float4*)&g_agg[n * FDIM];
#pragma unroll
    for (int qq = 0; qq < 4; qq++) {
        float4 v = ain[qq];
        a[qq*4+0] = fmaxf(v.x * di + __ldg(&b1[qq*4+0]), 0.0f);
        a[qq*4+1] = fmaxf(v.y * di + __ldg(&b1[qq*4+1]), 0.0f);
        a[qq*4+2] = fmaxf(v.z * di + __ldg(&b1[qq*4+2]), 0.0f);
        a[qq*4+3] = fmaxf(v.w * di + __ldg(&b1[qq*4+3]), 0.0f);
    }
    float s[FDIM];
#pragma unroll
    for (int f = 0; f < FDIM; f++) {
        float acc = 0.0f;
#pragma unroll
        for (int k = 0; k < FDIM; k++) acc += a[k] * sW[k * FDIM + f];
        s[f] = acc;
    }
    store_h16(&g_h[n * FDIM], s, di);
    float4* ap = (float4*)&g_agg[n * FDIM];
#pragma unroll
    for (int qq = 0; qq < 4; qq++)
        ap[qq] = make_float4(s[qq*4+0]*di, s[qq*4+1]*di, s[qq*4+2]*di, s[qq*4+3]*di);
}

// 6) pool: relu(agg*di + b2) -> red.v4 per graph; 4 lanes/node
__global__ void k_pool(const int* __restrict__ batch,
                       const float* __restrict__ b2, int N) {
    long long idx = (long long)blockIdx.x * blockDim.x + threadIdx.x;
    int n = (int)(idx >> 2);
    int q = (int)(idx & 3);
    if (n >= N) return;
    float di = rsqrtf((float)g_cnt_i[n] + 1.0f);
    int g = __ldg(&batch[n]);
    float4 v = *(const float4*)&g_agg[n * FDIM + q * 4];
    float4 a = make_float4(fmaxf(v.x * di + __ldg(&b2[q*4+0]), 0.0f),
                           fmaxf(v.y * di + __ldg(&b2[q*4+1]), 0.0f),
                           fmaxf(v.z * di + __ldg(&b2[q*4+2]), 0.0f),
                           fmaxf(v.w * di + __ldg(&b2[q*4+3]), 0.0f));
    red_v4(&g_pool[g * FDIM + q * 4], a);
    if (q == 0) atomicAdd(&g_gcnt[g], 1.0f);
}

// 7) MLP head
__global__ void k_mlp(const float* __restrict__ meta,
                      const float* __restrict__ Wh1, const float* __restrict__ bh1,
                      const float* __restrict__ Wh2, const float* __restrict__ bh2,
                      float* __restrict__ out, int G) {
    int g = blockIdx.x * blockDim.x + threadIdx.x;
    if (g >= G) return;
    float inv = 1.0f / fmaxf(g_gcnt[g], 1.0f);
    float z[FDIM];
#pragma unroll
    for (int f = 0; f < FDIM; f++) z[f] = __ldg(&bh1[f]);
#pragma unroll
    for (int k = 0; k < FDIM; k++) {
        float e = g_pool[g * FDIM + k] * inv;
#pragma unroll
        for (int f = 0; f < FDIM; f++) z[f] += e * __ldg(&Wh1[k * FDIM + f]);
    }
    for (int k = 0; k < 27; k++) {
        float m = meta[g * 27 + k];
#pragma unroll
        for (int f = 0; f < FDIM; f++) z[f] += m * __ldg(&Wh1[(FDIM + k) * FDIM + f]);
    }
    float o = __ldg(&bh2[0]);
#pragma unroll
    for (int f = 0; f < FDIM; f++) o += fmaxf(z[f], 0.0f) * __ldg(&Wh2[f]);
    out[g] = o;
}

extern "C" void kernel_launch(void* const* d_in, const int* in_sizes, int n_in,
                              void* d_out, int out_size) {
    const float* x    = (const float*)d_in[0];
    const int*   ei   = (const int*)d_in[1];
    const int*   batch= (const int*)d_in[2];
    const float* meta = (const float*)d_in[3];
    const float* W1   = (const float*)d_in[4];
    const float* b1   = (const float*)d_in[5];
    const float* W2   = (const float*)d_in[6];
    const float* b2   = (const float*)d_in[7];
    const float* Wh1  = (const float*)d_in[8];
    const float* bh1  = (const float*)d_in[9];
    const float* Wh2  = (const float*)d_in[10];
    const float* bh2  = (const float*)d_in[11];
    float* out = (float*)d_out;

    const int N = in_sizes[0] / 9;
    const int E = in_sizes[1] / 2;
    const int G = in_sizes[3] / 27;
    const int* rows = ei;      // source
    const int* cols = ei + E;  // target

    const int B = 256;

    void *p_cnt, *p_pool, *p_gcnt;
    cudaGetSymbolAddress(&p_cnt, g_cnt_i);
    cudaGetSymbolAddress(&p_pool, g_pool);
    cudaGetSymbolAddress(&p_gcnt, g_gcnt);
    cudaMemsetAsync(p_cnt, 0, (size_t)N * sizeof(int));
    cudaMemsetAsync(p_pool, 0, (size_t)G * FDIM * sizeof(float));
    cudaMemsetAsync(p_gcnt, 0, (size_t)G * sizeof(float));

    k_count<<<(E + B - 1) / B, B>>>(cols, E);
    k_layer1<<<(N + 127) / 128, 128>>>(x, W1, N);
    {
        long long t = (long long)E * 4;
        int nb = (int)((t + B - 1) / B);
        k_scatter<<<nb, B>>>(rows, cols, E);
        k_transform<<<(N + B - 1) / B, B>>>(b1, W2, N);
        k_scatter<<<nb, B>>>(rows, cols, E);
    }
    {
        long long t = (long long)N * 4;
        k_pool<<<(int)((t + B - 1) / B), B>>>(batch, b2, N);
    }
    k_mlp<<<(G + B - 1) / B, B>>>(meta, Wh1, bh1, Wh2, bh2, out, G);
}

// round 9
// speedup vs baseline: 2.0407x; 1.3307x over previous
#include <cuda_runtime.h>
#include <cuda_fp16.h>

#define MAX_NODES 500000
#define MAX_GRAPHS 8192
#define FDIM 16

__device__ int    g_cnt_i[MAX_NODES];            // in-degree (memset 0)
__device__ __half g_h[MAX_NODES * FDIM];         // features * dinv (fp16)
__device__ __half g_agg_h[MAX_NODES * FDIM];     // fp16 accumulator (init=self term)
__device__ float  g_pool[MAX_GRAPHS * FDIM];
__device__ float  g_gcnt[MAX_GRAPHS];

__device__ __forceinline__ void red_v4f(float* addr, float4 v) {
    asm volatile("red.global.add.v4.f32 [%0], {%1,%2,%3,%4};"
                 :: "l"(addr), "f"(v.x), "f"(v.y), "f"(v.z), "f"(v.w)
                 : "memory");
}

// vector fp16x2 atomic add: 8 halves (16B) in one lane
__device__ __forceinline__ void red_v4h2(__half* addr, uint4 u) {
    asm volatile("red.global.add.noftz.v4.f16x2 [%0], {%1,%2,%3,%4};"
                 :: "l"(addr), "r"(u.x), "r"(u.y), "r"(u.z), "r"(u.w)
                 : "memory");
}

// pack 16 scaled fp32 -> 32B fp16
__device__ __forceinline__ void store_h16(__half* dst, const float* s, float di) {
    __align__(16) __half2 hh[8];
#pragma unroll
    for (int q = 0; q < 8; q++)
        hh[q] = __floats2half2_rn(s[2 * q] * di, s[2 * q + 1] * di);
    *(uint4*)dst       = *(uint4*)&hh[0];
    *(uint4*)(dst + 8) = *(uint4*)&hh[4];
}

// load 16 fp16 -> fp32
__device__ __forceinline__ void load_h16(const __half* src, float* f) {
    uint4 u0 = *(const uint4*)src;
    uint4 u1 = *(const uint4*)(src + 8);
    const unsigned* uu[8] = {&u0.x,&u0.y,&u0.z,&u0.w,&u1.x,&u1.y,&u1.z,&u1.w};
#pragma unroll
    for (int q = 0; q < 8; q++) {
        float2 p = __half22float2(*(const __half2*)uu[q]);
        f[2*q] = p.x; f[2*q+1] = p.y;
    }
}

// 1) in-degree count over targets
__global__ void k_count(const int* __restrict__ cols, int E) {
    int e = blockIdx.x * blockDim.x + threadIdx.x;
    if (e < E) atomicAdd(&g_cnt_i[cols[e]], 1);
}

// 2) layer1: s = x@W1 ; g_h = g_agg_h = fp16(s*di)
__global__ void k_layer1(const float* __restrict__ x, const float* __restrict__ W1,
                         int N) {
    __shared__ float sx[128 * 9];
    int base = blockIdx.x * 128;
    int n = base + threadIdx.x;
    int lim = min(128, N - base) * 9;
    for (int i = threadIdx.x; i < lim; i += 128)
        sx[i] = x[(long long)base * 9 + i];
    __syncthreads();
    if (n >= N) return;
    float xi[9];
#pragma unroll
    for (int k = 0; k < 9; k++) xi[k] = sx[threadIdx.x * 9 + k];
    float di = rsqrtf((float)g_cnt_i[n] + 1.0f);
    float s[FDIM];
#pragma unroll
    for (int f = 0; f < FDIM; f++) {
        float acc = 0.0f;
#pragma unroll
        for (int k = 0; k < 9; k++) acc += xi[k] * __ldg(&W1[k * FDIM + f]);
        s[f] = acc;
    }
    store_h16(&g_h[n * FDIM], s, di);
    store_h16(&g_agg_h[n * FDIM], s, di);
}

// 3/5) scatter: agg[c] += g_h[r]; 2 lanes/edge, 16B fp16 load + one v4.f16x2 red
__global__ void k_scatter(const int* __restrict__ rows,
                          const int* __restrict__ cols, int E) {
    long long idx = (long long)blockIdx.x * blockDim.x + threadIdx.x;
    int e = (int)(idx >> 1);
    int q = (int)(idx & 1);
    if (e >= E) return;
    int r = __ldg(&rows[e]);
    int c = __ldg(&cols[e]);
    uint4 u = *(const uint4*)&g_h[r * FDIM + q * 8];
    red_v4h2(&g_agg_h[c * FDIM + q * 8], u);
}

// 4) transform: a = relu(agg*di + b1); s = a@W2; g_h = g_agg_h = fp16(s*di)
__global__ void k_transform(const float* __restrict__ b1, const float* __restrict__ W2,
                            int N) {
    __shared__ float sW[FDIM * FDIM];
    if (threadIdx.x < FDIM * FDIM) sW[threadIdx.x] = W2[threadIdx.x];
    __syncthreads();
    int n = blockIdx.x * blockDim.x + threadIdx.x;
    if (n >= N) return;
    float di = rsqrtf((float)g_cnt_i[n] + 1.0f);
    float f[FDIM], a[FDIM];
    load_h16(&g_agg_h[n * FDIM], f);
#pragma unroll
    for (int k = 0; k < FDIM; k++)
        a[k] = fmaxf(f[k] * di + __ldg(&b1[k]), 0.0f);
    float s[FDIM];
#pragma unroll
    for (int ff = 0; ff < FDIM; ff++) {
        float acc = 0.0f;
#pragma unroll
        for (int k = 0; k < FDIM; k++) acc += a[k] * sW[k * FDIM + ff];
        s[ff] = acc;
    }
    store_h16(&g_h[n * FDIM], s, di);
    store_h16(&g_agg_h[n * FDIM], s, di);
}

// 6) pool: relu(agg*di + b2) -> fp32 red.v4 per graph; 4 lanes/node
__global__ void k_pool(const int* __restrict__ batch,
                       const float* __restrict__ b2, int N) {
    long long idx = (long long)blockIdx.x * blockDim.x + threadIdx.x;
    int n = (int)(idx >> 2);
    int q = (int)(idx & 3);
    if (n >= N) return;
    float di = rsqrtf((float)g_cnt_i[n] + 1.0f);
    int g = __ldg(&batch[n]);
    uint2 u = *(const uint2*)&g_agg_h[n * FDIM + q * 4];
    float2 f0 = __half22float2(*(__half2*)&u.x);
    float2 f1 = __half22float2(*(__half2*)&u.y);
    float4 a = make_float4(fmaxf(f0.x * di + __ldg(&b2[q*4+0]), 0.0f),
                           fmaxf(f0.y * di + __ldg(&b2[q*4+1]), 0.0f),
                           fmaxf(f1.x * di + __ldg(&b2[q*4+2]), 0.0f),
                           fmaxf(f1.y * di + __ldg(&b2[q*4+3]), 0.0f));
    red_v4f(&g_pool[g * FDIM + q * 4], a);
    if (q == 0) atomicAdd(&g_gcnt[g], 1.0f);
}

// 7) MLP head
__global__ void k_mlp(const float* __restrict__ meta,
                      const float* __restrict__ Wh1, const float* __restrict__ bh1,
                      const float* __restrict__ Wh2, const float* __restrict__ bh2,
                      float* __restrict__ out, int G) {
    int g = blockIdx.x * blockDim.x + threadIdx.x;
    if (g >= G) return;
    float inv = 1.0f / fmaxf(g_gcnt[g], 1.0f);
    float z[FDIM];
#pragma unroll
    for (int f = 0; f < FDIM; f++) z[f] = __ldg(&bh1[f]);
#pragma unroll
    for (int k = 0; k < FDIM; k++) {
        float e = g_pool[g * FDIM + k] * inv;
#pragma unroll
        for (int f = 0; f < FDIM; f++) z[f] += e * __ldg(&Wh1[k * FDIM + f]);
    }
    for (int k = 0; k < 27; k++) {
        float m = meta[g * 27 + k];
#pragma unroll
        for (int f = 0; f < FDIM; f++) z[f] += m * __ldg(&Wh1[(FDIM + k) * FDIM + f]);
    }
    float o = __ldg(&bh2[0]);
#pragma unroll
    for (int f = 0; f < FDIM; f++) o += fmaxf(z[f], 0.0f) * __ldg(&Wh2[f]);
    out[g] = o;
}

extern "C" void kernel_launch(void* const* d_in, const int* in_sizes, int n_in,
                              void* d_out, int out_size) {
    const float* x    = (const float*)d_in[0];
    const int*   ei   = (const int*)d_in[1];
    const int*   batch= (const int*)d_in[2];
    const float* meta = (const float*)d_in[3];
    const float* W1   = (const float*)d_in[4];
    const float* b1   = (const float*)d_in[5];
    const float* W2   = (const float*)d_in[6];
    const float* b2   = (const float*)d_in[7];
    const float* Wh1  = (const float*)d_in[8];
    const float* bh1  = (const float*)d_in[9];
    const float* Wh2  = (const float*)d_in[10];
    const float* bh2  = (const float*)d_in[11];
    float* out = (float*)d_out;

    const int N = in_sizes[0] / 9;
    const int E = in_sizes[1] / 2;
    const int G = in_sizes[3] / 27;
    const int* rows = ei;      // source
    const int* cols = ei + E;  // target

    const int B = 256;

    void *p_cnt, *p_pool, *p_gcnt;
    cudaGetSymbolAddress(&p_cnt, g_cnt_i);
    cudaGetSymbolAddress(&p_pool, g_pool);
    cudaGetSymbolAddress(&p_gcnt, g_gcnt);
    cudaMemsetAsync(p_cnt, 0, (size_t)N * sizeof(int));
    cudaMemsetAsync(p_pool, 0, (size_t)G * FDIM * sizeof(float));
    cudaMemsetAsync(p_gcnt, 0, (size_t)G * sizeof(float));

    k_count<<<(E + B - 1) / B, B>>>(cols, E);
    k_layer1<<<(N + 127) / 128, 128>>>(x, W1, N);
    {
        long long t = (long long)E * 2;
        int nb = (int)((t + B - 1) / B);
        k_scatter<<<nb, B>>>(rows, cols, E);
        k_transform<<<(N + B - 1) / B, B>>>(b1, W2, N);
        k_scatter<<<nb, B>>>(rows, cols, E);
    }
    {
        long long t = (long long)N * 4;
        k_pool<<<(int)((t + B - 1) / B), B>>>(batch, b2, N);
    }
    k_mlp<<<(G + B - 1) / B, B>>>(meta, Wh1, bh1, Wh2, bh2, out, G);
}